// round 7
// baseline (speedup 1.0000x reference)
#include <cuda_runtime.h>
#include <math.h>
#include <stdint.h>

#define NUM_HEADS 16
#define DHEAD 64
#define DE 128          // 2*DHEAD per head
#define DMODEL 1024
#define D2 2048
#define BB 4
#define NN 1024
#define MTOT (BB*NN)    // 4096
#define QKP 132         // smem pitch for Q/K tiles (132 mod 32 = 4 -> bijective frag banks)
#define VP  136         // smem pitch for V tile (136 mod 32 = 8 -> bijective B-frag banks)
#define PP  68          // smem pitch for P tiles (68 mod 32 = 4 -> bijective A-frag banks)
#define GP2 20          // GEMM smem pitch for BK=16 (20*fr mod 32 distinct -> conflict-free frags)

// Scratch (device globals; allocation APIs are forbidden)
__device__ float g_Q[(size_t)BB*NUM_HEADS*NN*DE];
__device__ float g_K[(size_t)BB*NUM_HEADS*NN*DE];
__device__ float g_V[(size_t)BB*NUM_HEADS*NN*DE];
__device__ float g_Oc[(size_t)BB*NN*D2];
__device__ float g_lam[NUM_HEADS];

__device__ __forceinline__ uint32_t f2tf(float f) {
    uint32_t u;
    asm("cvt.rna.tf32.f32 %0, %1;" : "=r"(u) : "f"(f));
    return u;
}

__device__ __forceinline__ void mma_tf32(float* d, const uint32_t* a, const uint32_t* b) {
    asm volatile(
        "mma.sync.aligned.m16n8k8.row.col.f32.tf32.tf32.f32 "
        "{%0,%1,%2,%3}, {%4,%5,%6,%7}, {%8,%9}, {%0,%1,%2,%3};"
        : "+f"(d[0]), "+f"(d[1]), "+f"(d[2]), "+f"(d[3])
        : "r"(a[0]), "r"(a[1]), "r"(a[2]), "r"(a[3]), "r"(b[0]), "r"(b[1]));
}

// ---------------------------------------------------------------------------
// lambda[h]
// ---------------------------------------------------------------------------
__global__ void lambda_kernel(const float* __restrict__ lq1, const float* __restrict__ lk1,
                              const float* __restrict__ lq2, const float* __restrict__ lk2) {
    int w = threadIdx.x >> 5, lane = threadIdx.x & 31;
    int base = w * 64;
    float s1 = lq1[base+lane]*lk1[base+lane] + lq1[base+32+lane]*lk1[base+32+lane];
    float s2 = lq2[base+lane]*lk2[base+lane] + lq2[base+32+lane]*lk2[base+32+lane];
    #pragma unroll
    for (int off = 16; off; off >>= 1) {
        s1 += __shfl_xor_sync(0xffffffffu, s1, off);
        s2 += __shfl_xor_sync(0xffffffffu, s2, off);
    }
    if (lane == 0) g_lam[w] = expf(s1) - expf(s2) + 0.8f;
}

// ---------------------------------------------------------------------------
// tf32 tensor-core GEMM, double-buffered: C[M,N] = A[M,K] @ W[N,K]^T (NT)
// 128x128x16 block tile, 2-stage smem, ONE barrier per k-iter.
// 256 threads = 8 warps of 64(M)x32(N).
// MODE 0: C row-major (ld = DMODEL). MODE 1: fused QKV scatter.
// ---------------------------------------------------------------------------
template<int MODE>
__global__ __launch_bounds__(256, 2) void gemm_tf32(
    const float* __restrict__ A,
    const float* __restrict__ B0, const float* __restrict__ B1, const float* __restrict__ B2,
    float* __restrict__ C0, float* __restrict__ C1, float* __restrict__ C2,
    int K)
{
    __shared__ float As[2][128][GP2];
    __shared__ float Bs[2][128][GP2];

    int t = threadIdx.x;
    int wid = t >> 5, lane = t & 31;
    int row0 = blockIdx.y * 128;

    const float* Bm;
    float* C;
    int col0;
    if (MODE == 1) {
        int which = blockIdx.x >> 4;
        col0 = (blockIdx.x & 15) * 128;
        Bm = (which == 0) ? B0 : ((which == 1) ? B1 : B2);
        C  = (which == 0) ? C0 : ((which == 1) ? C1 : C2);
    } else {
        col0 = blockIdx.x * 128;
        Bm = B0; C = C0;
    }

    // staging: thread t handles row t>>1, k-offset (t&1)*8, two float4 per operand
    int r0 = t >> 1;
    int kq = (t & 1) * 8;
    const float* Ag = A  + (size_t)(row0 + r0) * K + kq;
    const float* Bg = Bm + (size_t)(col0 + r0) * K + kq;

    float acc[4][4][4];
    #pragma unroll
    for (int i = 0; i < 4; i++)
        #pragma unroll
        for (int j = 0; j < 4; j++)
            #pragma unroll
            for (int r = 0; r < 4; r++) acc[i][j][r] = 0.f;

    int wm = (wid & 1) * 64;
    int wn = (wid >> 1) * 32;
    int fr = lane >> 2;
    int fc = lane & 3;

    // preload + store stage 0
    {
        float4 a0 = *(const float4*)(Ag);
        float4 a1 = *(const float4*)(Ag + 4);
        float4 b0 = *(const float4*)(Bg);
        float4 b1 = *(const float4*)(Bg + 4);
        *(uint4*)&As[0][r0][kq]   = make_uint4(f2tf(a0.x), f2tf(a0.y), f2tf(a0.z), f2tf(a0.w));
        *(uint4*)&As[0][r0][kq+4] = make_uint4(f2tf(a1.x), f2tf(a1.y), f2tf(a1.z), f2tf(a1.w));
        *(uint4*)&Bs[0][r0][kq]   = make_uint4(f2tf(b0.x), f2tf(b0.y), f2tf(b0.z), f2tf(b0.w));
        *(uint4*)&Bs[0][r0][kq+4] = make_uint4(f2tf(b1.x), f2tf(b1.y), f2tf(b1.z), f2tf(b1.w));
    }
    __syncthreads();

    for (int k0 = 0; k0 < K; k0 += 16) {
        int cur = (k0 >> 4) & 1;
        bool more = (k0 + 16 < K);

        // issue next tile's global loads (consumed after mma below)
        float4 a0, a1, b0, b1;
        if (more) {
            a0 = *(const float4*)(Ag + k0 + 16);
            a1 = *(const float4*)(Ag + k0 + 20);
            b0 = *(const float4*)(Bg + k0 + 16);
            b1 = *(const float4*)(Bg + k0 + 20);
        }

        // mma on current stage: 2 k-chunks of 8
        #pragma unroll
        for (int kc = 0; kc < 16; kc += 8) {
            uint32_t af[4][4], bf[4][2];
            #pragma unroll
            for (int i = 0; i < 4; i++) {
                af[i][0] = __float_as_uint(As[cur][wm + i*16 +     fr][kc +     fc]);
                af[i][1] = __float_as_uint(As[cur][wm + i*16 + 8 + fr][kc +     fc]);
                af[i][2] = __float_as_uint(As[cur][wm + i*16 +     fr][kc + 4 + fc]);
                af[i][3] = __float_as_uint(As[cur][wm + i*16 + 8 + fr][kc + 4 + fc]);
            }
            #pragma unroll
            for (int j = 0; j < 4; j++) {
                bf[j][0] = __float_as_uint(Bs[cur][wn + j*8 + fr][kc +     fc]);
                bf[j][1] = __float_as_uint(Bs[cur][wn + j*8 + fr][kc + 4 + fc]);
            }
            #pragma unroll
            for (int i = 0; i < 4; i++)
                #pragma unroll
                for (int j = 0; j < 4; j++)
                    mma_tf32(acc[i][j], af[i], bf[j]);
        }

        // store next tile into the other stage
        if (more) {
            int nxt = cur ^ 1;
            *(uint4*)&As[nxt][r0][kq]   = make_uint4(f2tf(a0.x), f2tf(a0.y), f2tf(a0.z), f2tf(a0.w));
            *(uint4*)&As[nxt][r0][kq+4] = make_uint4(f2tf(a1.x), f2tf(a1.y), f2tf(a1.z), f2tf(a1.w));
            *(uint4*)&Bs[nxt][r0][kq]   = make_uint4(f2tf(b0.x), f2tf(b0.y), f2tf(b0.z), f2tf(b0.w));
            *(uint4*)&Bs[nxt][r0][kq+4] = make_uint4(f2tf(b1.x), f2tf(b1.y), f2tf(b1.z), f2tf(b1.w));
        }
        __syncthreads();
    }

    #pragma unroll
    for (int i = 0; i < 4; i++) {
        int rr = row0 + wm + i*16 + fr;
        #pragma unroll
        for (int j = 0; j < 4; j++) {
            int cc = col0 + wn + j*8 + fc*2;
            float2 v0 = make_float2(acc[i][j][0], acc[i][j][1]);
            float2 v1 = make_float2(acc[i][j][2], acc[i][j][3]);
            if (MODE == 0) {
                *(float2*)(C + (size_t)rr * DMODEL + cc) = v0;
                *(float2*)(C + (size_t)(rr + 8) * DMODEL + cc) = v1;
            } else {
                int h = cc >> 7, e = cc & 127;
                int bb = rr >> 10, n = rr & 1023;
                *(float2*)(C + (((size_t)(bb*NUM_HEADS + h) * NN + n) * DE + e)) = v0;
                int rr2 = rr + 8;
                bb = rr2 >> 10; n = rr2 & 1023;
                *(float2*)(C + (((size_t)(bb*NUM_HEADS + h) * NN + n) * DE + e)) = v1;
            }
        }
    }
}

// ---------------------------------------------------------------------------
// Fully-tensorized dual-stream flash attention (3xTF32 logits + tf32 PV).
// Grid: (N/64, B*H). 256 threads = 8 warps.
// Causal remap: blockIdx.x=0 takes the LONGEST query tile (best tail behavior).
// ---------------------------------------------------------------------------
__global__ __launch_bounds__(256) void attn_kernel(const float* __restrict__ rms_scale) {
    extern __shared__ float sm[];
    float* Qh  = sm;                       // 64 x QKP (tf32 hi)
    float* Ql  = Qh + 64*QKP;              // 64 x QKP (tf32 lo)
    float* Kh  = Ql + 64*QKP;
    float* Kl  = Kh + 64*QKP;
    float* Vs  = Kl + 64*QKP;              // 64 x VP (tf32)
    float* P1  = Vs + 64*VP;               // 64 x PP (tf32)
    float* P2  = P1 + 64*PP;
    float* bm1 = P2 + 64*PP;               // [2][64] row-max exchange
    float* bm2 = bm1 + 128;
    float* bs1 = bm2 + 128;                // [2][64] row-sum exchange
    float* bs2 = bs1 + 128;

    int t  = threadIdx.x;
    int bh = blockIdx.y;
    int h  = bh & (NUM_HEADS - 1);
    int b  = bh >> 4;
    int qi = gridDim.x - 1 - blockIdx.x;   // long tiles scheduled first
    int qb = qi * 64;
    const float* Qp = g_Q + (size_t)bh * NN * DE;
    const float* Kp = g_K + (size_t)bh * NN * DE;
    const float* Vp = g_V + (size_t)bh * NN * DE;

    int lane = t & 31, wid = t >> 5;
    int gid = lane >> 2, tig = lane & 3;
    int rt = (wid >> 1) * 16;
    int half = wid & 1;
    int ch = half * 32;     // score col-half
    int nh = half * 64;     // PV col-half
    int rA = rt + gid, rB = rt + gid + 8;

    // load Q tile (64x128), split hi/lo
    #pragma unroll
    for (int l = 0; l < 8; l++) {
        int c = t + l*256;
        int r = c >> 5, dq = (c & 31) * 4;
        float4 q = *(const float4*)(Qp + (size_t)(qb + r)*DE + dq);
        uint4 hi = make_uint4(f2tf(q.x), f2tf(q.y), f2tf(q.z), f2tf(q.w));
        uint4 lo = make_uint4(f2tf(q.x - __uint_as_float(hi.x)),
                              f2tf(q.y - __uint_as_float(hi.y)),
                              f2tf(q.z - __uint_as_float(hi.z)),
                              f2tf(q.w - __uint_as_float(hi.w)));
        *(uint4*)&Qh[r*QKP + dq] = hi;
        *(uint4*)&Ql[r*QKP + dq] = lo;
    }

    float m1a = -1e30f, m1b = -1e30f, m2a = -1e30f, m2b = -1e30f;
    float l1a = 0.f, l1b = 0.f, l2a = 0.f, l2b = 0.f;
    float o1[8][4], o2[8][4];
    #pragma unroll
    for (int f = 0; f < 8; f++)
        #pragma unroll
        for (int r = 0; r < 4; r++) { o1[f][r] = 0.f; o2[f][r] = 0.f; }

    float lam = g_lam[h];

    int nkb = qi + 1;   // causal: key blocks 0..qi
    for (int jb = 0; jb < nkb; jb++) {
        int kb = jb * 64;
        // load K (split hi/lo) and V (tf32) tiles
        #pragma unroll
        for (int l = 0; l < 8; l++) {
            int c = t + l*256;
            int r = c >> 5, dq = (c & 31) * 4;
            float4 kq = *(const float4*)(Kp + (size_t)(kb + r)*DE + dq);
            uint4 hi = make_uint4(f2tf(kq.x), f2tf(kq.y), f2tf(kq.z), f2tf(kq.w));
            uint4 lo = make_uint4(f2tf(kq.x - __uint_as_float(hi.x)),
                                  f2tf(kq.y - __uint_as_float(hi.y)),
                                  f2tf(kq.z - __uint_as_float(hi.z)),
                                  f2tf(kq.w - __uint_as_float(hi.w)));
            *(uint4*)&Kh[r*QKP + dq] = hi;
            *(uint4*)&Kl[r*QKP + dq] = lo;
            float4 vv = *(const float4*)(Vp + (size_t)(kb + r)*DE + dq);
            uint4 uv = make_uint4(f2tf(vv.x), f2tf(vv.y), f2tf(vv.z), f2tf(vv.w));
            *(uint4*)&Vs[r*VP + dq] = uv;
        }
        __syncthreads();

        // ---- logits via 3xTF32 mma ----
        float s1[4][4], s2[4][4];
        #pragma unroll
        for (int i = 0; i < 4; i++)
            #pragma unroll
            for (int j = 0; j < 4; j++) { s1[i][j] = 0.f; s2[i][j] = 0.f; }

        #pragma unroll
        for (int kc = 0; kc < 64; kc += 8) {
            uint32_t a1h[4], a1l[4], a2h[4], a2l[4];
            a1h[0] = __float_as_uint(Qh[rA*QKP + kc + tig]);
            a1h[1] = __float_as_uint(Qh[rB*QKP + kc + tig]);
            a1h[2] = __float_as_uint(Qh[rA*QKP + kc + tig + 4]);
            a1h[3] = __float_as_uint(Qh[rB*QKP + kc + tig + 4]);
            a1l[0] = __float_as_uint(Ql[rA*QKP + kc + tig]);
            a1l[1] = __float_as_uint(Ql[rB*QKP + kc + tig]);
            a1l[2] = __float_as_uint(Ql[rA*QKP + kc + tig + 4]);
            a1l[3] = __float_as_uint(Ql[rB*QKP + kc + tig + 4]);
            a2h[0] = __float_as_uint(Qh[rA*QKP + 64 + kc + tig]);
            a2h[1] = __float_as_uint(Qh[rB*QKP + 64 + kc + tig]);
            a2h[2] = __float_as_uint(Qh[rA*QKP + 64 + kc + tig + 4]);
            a2h[3] = __float_as_uint(Qh[rB*QKP + 64 + kc + tig + 4]);
            a2l[0] = __float_as_uint(Ql[rA*QKP + 64 + kc + tig]);
            a2l[1] = __float_as_uint(Ql[rB*QKP + 64 + kc + tig]);
            a2l[2] = __float_as_uint(Ql[rA*QKP + 64 + kc + tig + 4]);
            a2l[3] = __float_as_uint(Ql[rB*QKP + 64 + kc + tig + 4]);
            #pragma unroll
            for (int nt = 0; nt < 4; nt++) {
                int n0 = ch + nt*8 + gid;
                uint32_t b1h[2], b1l[2], b2h[2], b2l[2];
                b1h[0] = __float_as_uint(Kh[n0*QKP + kc + tig]);
                b1h[1] = __float_as_uint(Kh[n0*QKP + kc + tig + 4]);
                b1l[0] = __float_as_uint(Kl[n0*QKP + kc + tig]);
                b1l[1] = __float_as_uint(Kl[n0*QKP + kc + tig + 4]);
                b2h[0] = __float_as_uint(Kh[n0*QKP + 64 + kc + tig]);
                b2h[1] = __float_as_uint(Kh[n0*QKP + 64 + kc + tig + 4]);
                b2l[0] = __float_as_uint(Kl[n0*QKP + 64 + kc + tig]);
                b2l[1] = __float_as_uint(Kl[n0*QKP + 64 + kc + tig + 4]);
                mma_tf32(s1[nt], a1h, b1h);
                mma_tf32(s1[nt], a1l, b1h);
                mma_tf32(s1[nt], a1h, b1l);
                mma_tf32(s2[nt], a2h, b2h);
                mma_tf32(s2[nt], a2l, b2h);
                mma_tf32(s2[nt], a2h, b2l);
            }
        }

        // ---- scale (+ diagonal mask) ----
        bool last = (jb == nkb - 1);
        #pragma unroll
        for (int nt = 0; nt < 4; nt++)
            #pragma unroll
            for (int c = 0; c < 4; c++) {
                float v1 = s1[nt][c] * 0.125f;
                float v2 = s2[nt][c] * 0.125f;
                if (last) {
                    int col = ch + nt*8 + 2*tig + (c & 1);
                    int row = rt + gid + ((c & 2) ? 8 : 0);
                    if (col > row) { v1 = -1e30f; v2 = -1e30f; }
                }
                s1[nt][c] = v1; s2[nt][c] = v2;
            }

        // ---- row max (own 32 cols -> cross-half exchange) ----
        float mt1a = -1e30f, mt1b = -1e30f, mt2a = -1e30f, mt2b = -1e30f;
        #pragma unroll
        for (int nt = 0; nt < 4; nt++) {
            mt1a = fmaxf(mt1a, fmaxf(s1[nt][0], s1[nt][1]));
            mt1b = fmaxf(mt1b, fmaxf(s1[nt][2], s1[nt][3]));
            mt2a = fmaxf(mt2a, fmaxf(s2[nt][0], s2[nt][1]));
            mt2b = fmaxf(mt2b, fmaxf(s2[nt][2], s2[nt][3]));
        }
        #pragma unroll
        for (int off = 1; off <= 2; off <<= 1) {
            mt1a = fmaxf(mt1a, __shfl_xor_sync(0xffffffffu, mt1a, off));
            mt1b = fmaxf(mt1b, __shfl_xor_sync(0xffffffffu, mt1b, off));
            mt2a = fmaxf(mt2a, __shfl_xor_sync(0xffffffffu, mt2a, off));
            mt2b = fmaxf(mt2b, __shfl_xor_sync(0xffffffffu, mt2b, off));
        }
        if (tig == 0) {
            bm1[half*64 + rA] = mt1a; bm1[half*64 + rB] = mt1b;
            bm2[half*64 + rA] = mt2a; bm2[half*64 + rB] = mt2b;
        }
        __syncthreads();
        float M1a = fmaxf(m1a, fmaxf(bm1[rA], bm1[64 + rA]));
        float M1b = fmaxf(m1b, fmaxf(bm1[rB], bm1[64 + rB]));
        float M2a = fmaxf(m2a, fmaxf(bm2[rA], bm2[64 + rA]));
        float M2b = fmaxf(m2b, fmaxf(bm2[rB], bm2[64 + rB]));
        float c1a = __expf(m1a - M1a), c1b = __expf(m1b - M1b);
        float c2a = __expf(m2a - M2a), c2b = __expf(m2b - M2b);
        m1a = M1a; m1b = M1b; m2a = M2a; m2b = M2b;

        // ---- exp, write tf32 P, partial sums ----
        float ps1a = 0.f, ps1b = 0.f, ps2a = 0.f, ps2b = 0.f;
        #pragma unroll
        for (int nt = 0; nt < 4; nt++) {
            int colb = ch + nt*8 + 2*tig;
            float p0 = __uint_as_float(f2tf(__expf(s1[nt][0] - M1a)));
            float p1 = __uint_as_float(f2tf(__expf(s1[nt][1] - M1a)));
            float p2 = __uint_as_float(f2tf(__expf(s1[nt][2] - M1b)));
            float p3 = __uint_as_float(f2tf(__expf(s1[nt][3] - M1b)));
            ps1a += p0 + p1; ps1b += p2 + p3;
            *(float2*)&P1[rA*PP + colb] = make_float2(p0, p1);
            *(float2*)&P1[rB*PP + colb] = make_float2(p2, p3);
            float q0 = __uint_as_float(f2tf(__expf(s2[nt][0] - M2a)));
            float q1 = __uint_as_float(f2tf(__expf(s2[nt][1] - M2a)));
            float q2 = __uint_as_float(f2tf(__expf(s2[nt][2] - M2b)));
            float q3 = __uint_as_float(f2tf(__expf(s2[nt][3] - M2b)));
            ps2a += q0 + q1; ps2b += q2 + q3;
            *(float2*)&P2[rA*PP + colb] = make_float2(q0, q1);
            *(float2*)&P2[rB*PP + colb] = make_float2(q2, q3);
        }
        #pragma unroll
        for (int off = 1; off <= 2; off <<= 1) {
            ps1a += __shfl_xor_sync(0xffffffffu, ps1a, off);
            ps1b += __shfl_xor_sync(0xffffffffu, ps1b, off);
            ps2a += __shfl_xor_sync(0xffffffffu, ps2a, off);
            ps2b += __shfl_xor_sync(0xffffffffu, ps2b, off);
        }
        if (tig == 0) {
            bs1[half*64 + rA] = ps1a; bs1[half*64 + rB] = ps1b;
            bs2[half*64 + rA] = ps2a; bs2[half*64 + rB] = ps2b;
        }
        __syncthreads();
        l1a = l1a*c1a + bs1[rA] + bs1[64 + rA];
        l1b = l1b*c1b + bs1[rB] + bs1[64 + rB];
        l2a = l2a*c2a + bs2[rA] + bs2[64 + rA];
        l2b = l2b*c2b + bs2[rB] + bs2[64 + rB];

        // ---- P @ V on tensor cores ----
        #pragma unroll
        for (int f = 0; f < 8; f++) {
            o1[f][0] *= c1a; o1[f][1] *= c1a; o1[f][2] *= c1b; o1[f][3] *= c1b;
            o2[f][0] *= c2a; o2[f][1] *= c2a; o2[f][2] *= c2b; o2[f][3] *= c2b;
        }
        #pragma unroll
        for (int kc = 0; kc < 64; kc += 8) {
            uint32_t a1f[4], a2f[4];
            a1f[0] = __float_as_uint(P1[rA*PP + kc + tig]);
            a1f[1] = __float_as_uint(P1[rB*PP + kc + tig]);
            a1f[2] = __float_as_uint(P1[rA*PP + kc + tig + 4]);
            a1f[3] = __float_as_uint(P1[rB*PP + kc + tig + 4]);
            a2f[0] = __float_as_uint(P2[rA*PP + kc + tig]);
            a2f[1] = __float_as_uint(P2[rB*PP + kc + tig]);
            a2f[2] = __float_as_uint(P2[rA*PP + kc + tig + 4]);
            a2f[3] = __float_as_uint(P2[rB*PP + kc + tig + 4]);
            #pragma unroll
            for (int f = 0; f < 8; f++) {
                uint32_t bf[2];
                bf[0] = __float_as_uint(Vs[(kc + tig    )*VP + nh + f*8 + gid]);
                bf[1] = __float_as_uint(Vs[(kc + tig + 4)*VP + nh + f*8 + gid]);
                mma_tf32(o1[f], a1f, bf);
                mma_tf32(o2[f], a2f, bf);
            }
        }
        __syncthreads();
    }

    // ---- finalize: combine, RMS-norm, write Oc ----
    float il1a = 1.0f / l1a, il1b = 1.0f / l1b;
    float il2a = 1.0f / l2a, il2b = 1.0f / l2b;

    float ssA = 0.f, ssB = 0.f;
    #pragma unroll
    for (int f = 0; f < 8; f++) {
        o1[f][0] = o1[f][0]*il1a - lam*o2[f][0]*il2a;
        o1[f][1] = o1[f][1]*il1a - lam*o2[f][1]*il2a;
        o1[f][2] = o1[f][2]*il1b - lam*o2[f][2]*il2b;
        o1[f][3] = o1[f][3]*il1b - lam*o2[f][3]*il2b;
        ssA += o1[f][0]*o1[f][0] + o1[f][1]*o1[f][1];
        ssB += o1[f][2]*o1[f][2] + o1[f][3]*o1[f][3];
    }
    ssA += __shfl_xor_sync(0xffffffffu, ssA, 1);
    ssA += __shfl_xor_sync(0xffffffffu, ssA, 2);
    ssB += __shfl_xor_sync(0xffffffffu, ssB, 1);
    ssB += __shfl_xor_sync(0xffffffffu, ssB, 2);

    // cross-half reduction via bm1/bm2 (free after loop)
    if (tig == 0) {
        float* dst = half ? bm2 : bm1;
        dst[rA] = ssA;
        dst[rB] = ssB;
    }
    __syncthreads();
    float totA = bm1[rA] + bm2[rA];
    float totB = bm1[rB] + bm2[rB];
    float scA = rsqrtf(totA * (1.0f/128.0f) + 1e-5f) * 0.2f;
    float scB = rsqrtf(totB * (1.0f/128.0f) + 1e-5f) * 0.2f;

    size_t obaseA = ((size_t)b * NN + qb + rA) * D2 + h * DE;
    size_t obaseB = ((size_t)b * NN + qb + rB) * D2 + h * DE;
    #pragma unroll
    for (int f = 0; f < 8; f++) {
        int col = nh + f*8 + 2*tig;
        float2 rs = *(const float2*)(rms_scale + col);
        *(float2*)(g_Oc + obaseA + col) = make_float2(o1[f][0]*scA*rs.x, o1[f][1]*scA*rs.y);
        *(float2*)(g_Oc + obaseB + col) = make_float2(o1[f][2]*scB*rs.x, o1[f][3]*scB*rs.y);
    }
}

// ---------------------------------------------------------------------------
// Host launcher
// ---------------------------------------------------------------------------
#define ATTN_SMEM ((4*64*QKP + 64*VP + 2*64*PP + 4*128) * 4)   // 206848 bytes

extern "C" void kernel_launch(void* const* d_in, const int* in_sizes, int n_in,
                              void* d_out, int out_size) {
    const float* X   = (const float*)d_in[0];
    const float* Wq  = (const float*)d_in[1];
    const float* Wk  = (const float*)d_in[2];
    const float* Wv  = (const float*)d_in[3];
    const float* Wo  = (const float*)d_in[4];
    const float* lq1 = (const float*)d_in[5];
    const float* lk1 = (const float*)d_in[6];
    const float* lq2 = (const float*)d_in[7];
    const float* lk2 = (const float*)d_in[8];
    const float* rms = (const float*)d_in[9];

    float *pQ, *pK, *pV, *pOc;
    cudaGetSymbolAddress((void**)&pQ,  g_Q);
    cudaGetSymbolAddress((void**)&pK,  g_K);
    cudaGetSymbolAddress((void**)&pV,  g_V);
    cudaGetSymbolAddress((void**)&pOc, g_Oc);

    lambda_kernel<<<1, 512>>>(lq1, lk1, lq2, lk2);

    dim3 gqkv(48, MTOT/128);
    gemm_tf32<1><<<gqkv, 256>>>(X, Wq, Wk, Wv, pQ, pK, pV, DMODEL);

    cudaFuncSetAttribute(attn_kernel, cudaFuncAttributeMaxDynamicSharedMemorySize, ATTN_SMEM);
    attn_kernel<<<dim3(NN/64, BB*NUM_HEADS), 256, ATTN_SMEM>>>(rms);

    dim3 gout(DMODEL/128, MTOT/128);
    gemm_tf32<0><<<gout, 256>>>(pOc, Wo, nullptr, nullptr, (float*)d_out, nullptr, nullptr, D2);
}

// round 9
// speedup vs baseline: 1.3133x; 1.3133x over previous
#include <cuda_runtime.h>
#include <math.h>
#include <stdint.h>

#define NUM_HEADS 16
#define DHEAD 64
#define DE 128          // 2*DHEAD per head
#define DMODEL 1024
#define D2 2048
#define BB 4
#define NN 1024
#define MTOT (BB*NN)    // 4096
#define QKP 132         // smem pitch for Q/K tiles (132 mod 32 = 4 -> bijective frag banks)
#define VP  136         // smem pitch for V tile (136 mod 32 = 8 -> bijective B-frag banks)
#define PP  68          // smem pitch for P tiles (68 mod 32 = 4 -> bijective A-frag banks)
#define GP 36           // GEMM smem pitch (proven R5 config)

// Scratch (device globals; allocation APIs are forbidden)
__device__ float g_Q[(size_t)BB*NUM_HEADS*NN*DE];
__device__ float g_K[(size_t)BB*NUM_HEADS*NN*DE];
__device__ float g_V[(size_t)BB*NUM_HEADS*NN*DE];
__device__ float g_Oc[(size_t)BB*NN*D2];
__device__ float g_lam[NUM_HEADS];

__device__ __forceinline__ uint32_t f2tf(float f) {
    uint32_t u;
    asm("cvt.rna.tf32.f32 %0, %1;" : "=r"(u) : "f"(f));
    return u;
}

__device__ __forceinline__ void mma_tf32(float* d, const uint32_t* a, const uint32_t* b) {
    asm volatile(
        "mma.sync.aligned.m16n8k8.row.col.f32.tf32.tf32.f32 "
        "{%0,%1,%2,%3}, {%4,%5,%6,%7}, {%8,%9}, {%0,%1,%2,%3};"
        : "+f"(d[0]), "+f"(d[1]), "+f"(d[2]), "+f"(d[3])
        : "r"(a[0]), "r"(a[1]), "r"(a[2]), "r"(a[3]), "r"(b[0]), "r"(b[1]));
}

// ---------------------------------------------------------------------------
// lambda[h]
// ---------------------------------------------------------------------------
__global__ void lambda_kernel(const float* __restrict__ lq1, const float* __restrict__ lk1,
                              const float* __restrict__ lq2, const float* __restrict__ lk2) {
    int w = threadIdx.x >> 5, lane = threadIdx.x & 31;
    int base = w * 64;
    float s1 = lq1[base+lane]*lk1[base+lane] + lq1[base+32+lane]*lk1[base+32+lane];
    float s2 = lq2[base+lane]*lk2[base+lane] + lq2[base+32+lane]*lk2[base+32+lane];
    #pragma unroll
    for (int off = 16; off; off >>= 1) {
        s1 += __shfl_xor_sync(0xffffffffu, s1, off);
        s2 += __shfl_xor_sync(0xffffffffu, s2, off);
    }
    if (lane == 0) g_lam[w] = expf(s1) - expf(s2) + 0.8f;
}

// ---------------------------------------------------------------------------
// tf32 tensor-core GEMM (R5 proven version): C = A @ W^T (NT)
// 128x128x32 block tile, single-buffered smem + register prefetch.
// ---------------------------------------------------------------------------
template<int MODE>
__global__ __launch_bounds__(256, 2) void gemm_tf32(
    const float* __restrict__ A,
    const float* __restrict__ B0, const float* __restrict__ B1, const float* __restrict__ B2,
    float* __restrict__ C0, float* __restrict__ C1, float* __restrict__ C2,
    int K)
{
    __shared__ float As[128][GP];
    __shared__ float Bs[128][GP];

    int t = threadIdx.x;
    int wid = t >> 5, lane = t & 31;
    int row0 = blockIdx.y * 128;

    const float* Bm;
    float* C;
    int col0;
    if (MODE == 1) {
        int which = blockIdx.x >> 4;
        col0 = (blockIdx.x & 15) * 128;
        Bm = (which == 0) ? B0 : ((which == 1) ? B1 : B2);
        C  = (which == 0) ? C0 : ((which == 1) ? C1 : C2);
    } else {
        col0 = blockIdx.x * 128;
        Bm = B0; C = C0;
    }

    int r0 = t >> 3;
    int kq = (t & 7) * 4;
    const float* Ag = A  + (size_t)(row0 + r0) * K + kq;
    const float* Bg = Bm + (size_t)(col0 + r0) * K + kq;

    float4 ar[4], br[4];
    #pragma unroll
    for (int l = 0; l < 4; l++) {
        ar[l] = *(const float4*)(Ag + (size_t)l * 32 * K);
        br[l] = *(const float4*)(Bg + (size_t)l * 32 * K);
    }

    float acc[4][4][4];
    #pragma unroll
    for (int i = 0; i < 4; i++)
        #pragma unroll
        for (int j = 0; j < 4; j++)
            #pragma unroll
            for (int r = 0; r < 4; r++) acc[i][j][r] = 0.f;

    int wm = (wid & 1) * 64;
    int wn = (wid >> 1) * 32;
    int fr = lane >> 2;
    int fc = lane & 3;

    for (int k0 = 0; k0 < K; k0 += 32) {
        #pragma unroll
        for (int l = 0; l < 4; l++) {
            uint4 ua = make_uint4(f2tf(ar[l].x), f2tf(ar[l].y), f2tf(ar[l].z), f2tf(ar[l].w));
            *(uint4*)&As[r0 + l*32][kq] = ua;
            uint4 ub = make_uint4(f2tf(br[l].x), f2tf(br[l].y), f2tf(br[l].z), f2tf(br[l].w));
            *(uint4*)&Bs[r0 + l*32][kq] = ub;
        }
        __syncthreads();

        if (k0 + 32 < K) {
            #pragma unroll
            for (int l = 0; l < 4; l++) {
                ar[l] = *(const float4*)(Ag + (size_t)l * 32 * K + k0 + 32);
                br[l] = *(const float4*)(Bg + (size_t)l * 32 * K + k0 + 32);
            }
        }

        #pragma unroll
        for (int kc = 0; kc < 32; kc += 8) {
            uint32_t af[4][4], bf[4][2];
            #pragma unroll
            for (int i = 0; i < 4; i++) {
                af[i][0] = __float_as_uint(As[wm + i*16 +     fr][kc +     fc]);
                af[i][1] = __float_as_uint(As[wm + i*16 + 8 + fr][kc +     fc]);
                af[i][2] = __float_as_uint(As[wm + i*16 +     fr][kc + 4 + fc]);
                af[i][3] = __float_as_uint(As[wm + i*16 + 8 + fr][kc + 4 + fc]);
            }
            #pragma unroll
            for (int j = 0; j < 4; j++) {
                bf[j][0] = __float_as_uint(Bs[wn + j*8 + fr][kc +     fc]);
                bf[j][1] = __float_as_uint(Bs[wn + j*8 + fr][kc + 4 + fc]);
            }
            #pragma unroll
            for (int i = 0; i < 4; i++)
                #pragma unroll
                for (int j = 0; j < 4; j++)
                    mma_tf32(acc[i][j], af[i], bf[j]);
        }
        __syncthreads();
    }

    #pragma unroll
    for (int i = 0; i < 4; i++) {
        int rr = row0 + wm + i*16 + fr;
        #pragma unroll
        for (int j = 0; j < 4; j++) {
            int cc = col0 + wn + j*8 + fc*2;
            float2 v0 = make_float2(acc[i][j][0], acc[i][j][1]);
            float2 v1 = make_float2(acc[i][j][2], acc[i][j][3]);
            if (MODE == 0) {
                *(float2*)(C + (size_t)rr * DMODEL + cc) = v0;
                *(float2*)(C + (size_t)(rr + 8) * DMODEL + cc) = v1;
            } else {
                int h = cc >> 7, e = cc & 127;
                int bb = rr >> 10, n = rr & 1023;
                *(float2*)(C + (((size_t)(bb*NUM_HEADS + h) * NN + n) * DE + e)) = v0;
                int rr2 = rr + 8;
                bb = rr2 >> 10; n = rr2 & 1023;
                *(float2*)(C + (((size_t)(bb*NUM_HEADS + h) * NN + n) * DE + e)) = v1;
            }
        }
    }
}

// ---------------------------------------------------------------------------
// Fully-tensorized dual-stream flash attention (3xTF32 logits + tf32 PV).
// Deferred softmax denominator (per-thread partials, reduced once at end).
// P writes -> __syncthreads() -> PV: P is a CROSS-WARP dependency (each warp
// reads the sibling half-warp's P columns) and MUST be barrier-ordered.
// LPT remap: blockIdx.x=0 takes the longest query tile.
// Grid: (N/64, B*H). 256 threads = 8 warps.
// ---------------------------------------------------------------------------
__global__ __launch_bounds__(256) void attn_kernel(const float* __restrict__ rms_scale) {
    extern __shared__ float sm[];
    float* Qh  = sm;                       // 64 x QKP (tf32 hi)
    float* Ql  = Qh + 64*QKP;              // 64 x QKP (tf32 lo)
    float* Kh  = Ql + 64*QKP;
    float* Kl  = Kh + 64*QKP;
    float* Vs  = Kl + 64*QKP;              // 64 x VP (tf32)
    float* P1  = Vs + 64*VP;               // 64 x PP (tf32)
    float* P2  = P1 + 64*PP;
    float* bm1 = P2 + 64*PP;               // [2][64] row-max exchange (loop) / ss exchange (end)
    float* bm2 = bm1 + 128;
    float* bs1 = bm2 + 128;                // [2][64] final l exchange
    float* bs2 = bs1 + 128;

    int t  = threadIdx.x;
    int bh = blockIdx.y;
    int h  = bh & (NUM_HEADS - 1);
    int b  = bh >> 4;
    int qi = gridDim.x - 1 - blockIdx.x;   // LPT: long tiles first
    int qb = qi * 64;
    const float* Qp = g_Q + (size_t)bh * NN * DE;
    const float* Kp = g_K + (size_t)bh * NN * DE;
    const float* Vp = g_V + (size_t)bh * NN * DE;

    int lane = t & 31, wid = t >> 5;
    int gid = lane >> 2, tig = lane & 3;
    int rt = (wid >> 1) * 16;
    int half = wid & 1;
    int ch = half * 32;     // score col-half
    int nh = half * 64;     // PV col-half
    int rA = rt + gid, rB = rt + gid + 8;

    // load Q tile (64x128), split hi/lo
    #pragma unroll
    for (int l = 0; l < 8; l++) {
        int c = t + l*256;
        int r = c >> 5, dq = (c & 31) * 4;
        float4 q = *(const float4*)(Qp + (size_t)(qb + r)*DE + dq);
        uint4 hi = make_uint4(f2tf(q.x), f2tf(q.y), f2tf(q.z), f2tf(q.w));
        uint4 lo = make_uint4(f2tf(q.x - __uint_as_float(hi.x)),
                              f2tf(q.y - __uint_as_float(hi.y)),
                              f2tf(q.z - __uint_as_float(hi.z)),
                              f2tf(q.w - __uint_as_float(hi.w)));
        *(uint4*)&Qh[r*QKP + dq] = hi;
        *(uint4*)&Ql[r*QKP + dq] = lo;
    }

    float m1a = -1e30f, m1b = -1e30f, m2a = -1e30f, m2b = -1e30f;
    float l1a = 0.f, l1b = 0.f, l2a = 0.f, l2b = 0.f;   // per-thread partials
    float o1[8][4], o2[8][4];
    #pragma unroll
    for (int f = 0; f < 8; f++)
        #pragma unroll
        for (int r = 0; r < 4; r++) { o1[f][r] = 0.f; o2[f][r] = 0.f; }

    float lam = g_lam[h];

    int nkb = qi + 1;   // causal: key blocks 0..qi
    for (int jb = 0; jb < nkb; jb++) {
        int kb = jb * 64;
        // load K (split hi/lo) and V (tf32) tiles
        #pragma unroll
        for (int l = 0; l < 8; l++) {
            int c = t + l*256;
            int r = c >> 5, dq = (c & 31) * 4;
            float4 kq = *(const float4*)(Kp + (size_t)(kb + r)*DE + dq);
            uint4 hi = make_uint4(f2tf(kq.x), f2tf(kq.y), f2tf(kq.z), f2tf(kq.w));
            uint4 lo = make_uint4(f2tf(kq.x - __uint_as_float(hi.x)),
                                  f2tf(kq.y - __uint_as_float(hi.y)),
                                  f2tf(kq.z - __uint_as_float(hi.z)),
                                  f2tf(kq.w - __uint_as_float(hi.w)));
            *(uint4*)&Kh[r*QKP + dq] = hi;
            *(uint4*)&Kl[r*QKP + dq] = lo;
            float4 vv = *(const float4*)(Vp + (size_t)(kb + r)*DE + dq);
            uint4 uv = make_uint4(f2tf(vv.x), f2tf(vv.y), f2tf(vv.z), f2tf(vv.w));
            *(uint4*)&Vs[r*VP + dq] = uv;
        }
        __syncthreads();

        // ---- logits via 3xTF32 mma ----
        float s1[4][4], s2[4][4];
        #pragma unroll
        for (int i = 0; i < 4; i++)
            #pragma unroll
            for (int j = 0; j < 4; j++) { s1[i][j] = 0.f; s2[i][j] = 0.f; }

        #pragma unroll
        for (int kc = 0; kc < 64; kc += 8) {
            uint32_t a1h[4], a1l[4], a2h[4], a2l[4];
            a1h[0] = __float_as_uint(Qh[rA*QKP + kc + tig]);
            a1h[1] = __float_as_uint(Qh[rB*QKP + kc + tig]);
            a1h[2] = __float_as_uint(Qh[rA*QKP + kc + tig + 4]);
            a1h[3] = __float_as_uint(Qh[rB*QKP + kc + tig + 4]);
            a1l[0] = __float_as_uint(Ql[rA*QKP + kc + tig]);
            a1l[1] = __float_as_uint(Ql[rB*QKP + kc + tig]);
            a1l[2] = __float_as_uint(Ql[rA*QKP + kc + tig + 4]);
            a1l[3] = __float_as_uint(Ql[rB*QKP + kc + tig + 4]);
            a2h[0] = __float_as_uint(Qh[rA*QKP + 64 + kc + tig]);
            a2h[1] = __float_as_uint(Qh[rB*QKP + 64 + kc + tig]);
            a2h[2] = __float_as_uint(Qh[rA*QKP + 64 + kc + tig + 4]);
            a2h[3] = __float_as_uint(Qh[rB*QKP + 64 + kc + tig + 4]);
            a2l[0] = __float_as_uint(Ql[rA*QKP + 64 + kc + tig]);
            a2l[1] = __float_as_uint(Ql[rB*QKP + 64 + kc + tig]);
            a2l[2] = __float_as_uint(Ql[rA*QKP + 64 + kc + tig + 4]);
            a2l[3] = __float_as_uint(Ql[rB*QKP + 64 + kc + tig + 4]);
            #pragma unroll
            for (int nt = 0; nt < 4; nt++) {
                int n0 = ch + nt*8 + gid;
                uint32_t b1h[2], b1l[2], b2h[2], b2l[2];
                b1h[0] = __float_as_uint(Kh[n0*QKP + kc + tig]);
                b1h[1] = __float_as_uint(Kh[n0*QKP + kc + tig + 4]);
                b1l[0] = __float_as_uint(Kl[n0*QKP + kc + tig]);
                b1l[1] = __float_as_uint(Kl[n0*QKP + kc + tig + 4]);
                b2h[0] = __float_as_uint(Kh[n0*QKP + 64 + kc + tig]);
                b2h[1] = __float_as_uint(Kh[n0*QKP + 64 + kc + tig + 4]);
                b2l[0] = __float_as_uint(Kl[n0*QKP + 64 + kc + tig]);
                b2l[1] = __float_as_uint(Kl[n0*QKP + 64 + kc + tig + 4]);
                mma_tf32(s1[nt], a1h, b1h);
                mma_tf32(s1[nt], a1l, b1h);
                mma_tf32(s1[nt], a1h, b1l);
                mma_tf32(s2[nt], a2h, b2h);
                mma_tf32(s2[nt], a2l, b2h);
                mma_tf32(s2[nt], a2h, b2l);
            }
        }

        // ---- scale (+ diagonal mask) ----
        bool last = (jb == nkb - 1);
        #pragma unroll
        for (int nt = 0; nt < 4; nt++)
            #pragma unroll
            for (int c = 0; c < 4; c++) {
                float v1 = s1[nt][c] * 0.125f;
                float v2 = s2[nt][c] * 0.125f;
                if (last) {
                    int col = ch + nt*8 + 2*tig + (c & 1);
                    int row = rt + gid + ((c & 2) ? 8 : 0);
                    if (col > row) { v1 = -1e30f; v2 = -1e30f; }
                }
                s1[nt][c] = v1; s2[nt][c] = v2;
            }

        // ---- row max (own 32 cols -> cross-half exchange) ----
        float mt1a = -1e30f, mt1b = -1e30f, mt2a = -1e30f, mt2b = -1e30f;
        #pragma unroll
        for (int nt = 0; nt < 4; nt++) {
            mt1a = fmaxf(mt1a, fmaxf(s1[nt][0], s1[nt][1]));
            mt1b = fmaxf(mt1b, fmaxf(s1[nt][2], s1[nt][3]));
            mt2a = fmaxf(mt2a, fmaxf(s2[nt][0], s2[nt][1]));
            mt2b = fmaxf(mt2b, fmaxf(s2[nt][2], s2[nt][3]));
        }
        #pragma unroll
        for (int off = 1; off <= 2; off <<= 1) {
            mt1a = fmaxf(mt1a, __shfl_xor_sync(0xffffffffu, mt1a, off));
            mt1b = fmaxf(mt1b, __shfl_xor_sync(0xffffffffu, mt1b, off));
            mt2a = fmaxf(mt2a, __shfl_xor_sync(0xffffffffu, mt2a, off));
            mt2b = fmaxf(mt2b, __shfl_xor_sync(0xffffffffu, mt2b, off));
        }
        if (tig == 0) {
            bm1[half*64 + rA] = mt1a; bm1[half*64 + rB] = mt1b;
            bm2[half*64 + rA] = mt2a; bm2[half*64 + rB] = mt2b;
        }
        __syncthreads();
        float M1a = fmaxf(m1a, fmaxf(bm1[rA], bm1[64 + rA]));
        float M1b = fmaxf(m1b, fmaxf(bm1[rB], bm1[64 + rB]));
        float M2a = fmaxf(m2a, fmaxf(bm2[rA], bm2[64 + rA]));
        float M2b = fmaxf(m2b, fmaxf(bm2[rB], bm2[64 + rB]));
        float c1a = __expf(m1a - M1a), c1b = __expf(m1b - M1b);
        float c2a = __expf(m2a - M2a), c2b = __expf(m2b - M2b);
        m1a = M1a; m1b = M1b; m2a = M2a; m2b = M2b;

        // ---- exp, write tf32 P; per-thread partial l (deferred reduction) ----
        float ps1a = 0.f, ps1b = 0.f, ps2a = 0.f, ps2b = 0.f;
        #pragma unroll
        for (int nt = 0; nt < 4; nt++) {
            int colb = ch + nt*8 + 2*tig;
            float p0 = __uint_as_float(f2tf(__expf(s1[nt][0] - M1a)));
            float p1 = __uint_as_float(f2tf(__expf(s1[nt][1] - M1a)));
            float p2 = __uint_as_float(f2tf(__expf(s1[nt][2] - M1b)));
            float p3 = __uint_as_float(f2tf(__expf(s1[nt][3] - M1b)));
            ps1a += p0 + p1; ps1b += p2 + p3;
            *(float2*)&P1[rA*PP + colb] = make_float2(p0, p1);
            *(float2*)&P1[rB*PP + colb] = make_float2(p2, p3);
            float q0 = __uint_as_float(f2tf(__expf(s2[nt][0] - M2a)));
            float q1 = __uint_as_float(f2tf(__expf(s2[nt][1] - M2a)));
            float q2 = __uint_as_float(f2tf(__expf(s2[nt][2] - M2b)));
            float q3 = __uint_as_float(f2tf(__expf(s2[nt][3] - M2b)));
            ps2a += q0 + q1; ps2b += q2 + q3;
            *(float2*)&P2[rA*PP + colb] = make_float2(q0, q1);
            *(float2*)&P2[rB*PP + colb] = make_float2(q2, q3);
        }
        // deferred denominator: c identical across lanes & halves for a row.
        l1a = l1a*c1a + ps1a;
        l1b = l1b*c1b + ps1b;
        l2a = l2a*c2a + ps2a;
        l2b = l2b*c2b + ps2b;

        // P is read cross-warp in PV below — block-level ordering REQUIRED.
        __syncthreads();

        // ---- P @ V on tensor cores ----
        #pragma unroll
        for (int f = 0; f < 8; f++) {
            o1[f][0] *= c1a; o1[f][1] *= c1a; o1[f][2] *= c1b; o1[f][3] *= c1b;
            o2[f][0] *= c2a; o2[f][1] *= c2a; o2[f][2] *= c2b; o2[f][3] *= c2b;
        }
        #pragma unroll
        for (int kc = 0; kc < 64; kc += 8) {
            uint32_t a1f[4], a2f[4];
            a1f[0] = __float_as_uint(P1[rA*PP + kc + tig]);
            a1f[1] = __float_as_uint(P1[rB*PP + kc + tig]);
            a1f[2] = __float_as_uint(P1[rA*PP + kc + tig + 4]);
            a1f[3] = __float_as_uint(P1[rB*PP + kc + tig + 4]);
            a2f[0] = __float_as_uint(P2[rA*PP + kc + tig]);
            a2f[1] = __float_as_uint(P2[rB*PP + kc + tig]);
            a2f[2] = __float_as_uint(P2[rA*PP + kc + tig + 4]);
            a2f[3] = __float_as_uint(P2[rB*PP + kc + tig + 4]);
            #pragma unroll
            for (int f = 0; f < 8; f++) {
                uint32_t bf[2];
                bf[0] = __float_as_uint(Vs[(kc + tig    )*VP + nh + f*8 + gid]);
                bf[1] = __float_as_uint(Vs[(kc + tig + 4)*VP + nh + f*8 + gid]);
                mma_tf32(o1[f], a1f, bf);
                mma_tf32(o2[f], a2f, bf);
            }
        }
        __syncthreads();
    }

    // ---- finalize: reduce l (tig lanes, then halves), combine, RMS, write ----
    #pragma unroll
    for (int off = 1; off <= 2; off <<= 1) {
        l1a += __shfl_xor_sync(0xffffffffu, l1a, off);
        l1b += __shfl_xor_sync(0xffffffffu, l1b, off);
        l2a += __shfl_xor_sync(0xffffffffu, l2a, off);
        l2b += __shfl_xor_sync(0xffffffffu, l2b, off);
    }
    if (tig == 0) {
        bs1[half*64 + rA] = l1a; bs1[half*64 + rB] = l1b;
        bs2[half*64 + rA] = l2a; bs2[half*64 + rB] = l2b;
    }
    __syncthreads();
    float il1a = 1.0f / (bs1[rA] + bs1[64 + rA]);
    float il1b = 1.0f / (bs1[rB] + bs1[64 + rB]);
    float il2a = 1.0f / (bs2[rA] + bs2[64 + rA]);
    float il2b = 1.0f / (bs2[rB] + bs2[64 + rB]);

    float ssA = 0.f, ssB = 0.f;
    #pragma unroll
    for (int f = 0; f < 8; f++) {
        o1[f][0] = o1[f][0]*il1a - lam*o2[f][0]*il2a;
        o1[f][1] = o1[f][1]*il1a - lam*o2[f][1]*il2a;
        o1[f][2] = o1[f][2]*il1b - lam*o2[f][2]*il2b;
        o1[f][3] = o1[f][3]*il1b - lam*o2[f][3]*il2b;
        ssA += o1[f][0]*o1[f][0] + o1[f][1]*o1[f][1];
        ssB += o1[f][2]*o1[f][2] + o1[f][3]*o1[f][3];
    }
    ssA += __shfl_xor_sync(0xffffffffu, ssA, 1);
    ssA += __shfl_xor_sync(0xffffffffu, ssA, 2);
    ssB += __shfl_xor_sync(0xffffffffu, ssB, 1);
    ssB += __shfl_xor_sync(0xffffffffu, ssB, 2);

    // cross-half reduction via bm1/bm2 (free after loop)
    if (tig == 0) {
        float* dst = half ? bm2 : bm1;
        dst[rA] = ssA;
        dst[rB] = ssB;
    }
    __syncthreads();
    float totA = bm1[rA] + bm2[rA];
    float totB = bm1[rB] + bm2[rB];
    float scA = rsqrtf(totA * (1.0f/128.0f) + 1e-5f) * 0.2f;
    float scB = rsqrtf(totB * (1.0f/128.0f) + 1e-5f) * 0.2f;

    size_t obaseA = ((size_t)b * NN + qb + rA) * D2 + h * DE;
    size_t obaseB = ((size_t)b * NN + qb + rB) * D2 + h * DE;
    #pragma unroll
    for (int f = 0; f < 8; f++) {
        int col = nh + f*8 + 2*tig;
        float2 rs = *(const float2*)(rms_scale + col);
        *(float2*)(g_Oc + obaseA + col) = make_float2(o1[f][0]*scA*rs.x, o1[f][1]*scA*rs.y);
        *(float2*)(g_Oc + obaseB + col) = make_float2(o1[f][2]*scB*rs.x, o1[f][3]*scB*rs.y);
    }
}

// ---------------------------------------------------------------------------
// Host launcher
// ---------------------------------------------------------------------------
#define ATTN_SMEM ((4*64*QKP + 64*VP + 2*64*PP + 4*128) * 4)   // 206848 bytes

extern "C" void kernel_launch(void* const* d_in, const int* in_sizes, int n_in,
                              void* d_out, int out_size) {
    const float* X   = (const float*)d_in[0];
    const float* Wq  = (const float*)d_in[1];
    const float* Wk  = (const float*)d_in[2];
    const float* Wv  = (const float*)d_in[3];
    const float* Wo  = (const float*)d_in[4];
    const float* lq1 = (const float*)d_in[5];
    const float* lk1 = (const float*)d_in[6];
    const float* lq2 = (const float*)d_in[7];
    const float* lk2 = (const float*)d_in[8];
    const float* rms = (const float*)d_in[9];

    float *pQ, *pK, *pV, *pOc;
    cudaGetSymbolAddress((void**)&pQ,  g_Q);
    cudaGetSymbolAddress((void**)&pK,  g_K);
    cudaGetSymbolAddress((void**)&pV,  g_V);
    cudaGetSymbolAddress((void**)&pOc, g_Oc);

    lambda_kernel<<<1, 512>>>(lq1, lk1, lq2, lk2);

    dim3 gqkv(48, MTOT/128);
    gemm_tf32<1><<<gqkv, 256>>>(X, Wq, Wk, Wv, pQ, pK, pV, DMODEL);

    cudaFuncSetAttribute(attn_kernel, cudaFuncAttributeMaxDynamicSharedMemorySize, ATTN_SMEM);
    attn_kernel<<<dim3(NN/64, BB*NUM_HEADS), 256, ATTN_SMEM>>>(rms);

    dim3 gout(DMODEL/128, MTOT/128);
    gemm_tf32<0><<<gout, 256>>>(pOc, Wo, nullptr, nullptr, (float*)d_out, nullptr, nullptr, D2);
}

// round 10
// speedup vs baseline: 1.4253x; 1.0853x over previous
#include <cuda_runtime.h>
#include <cuda_bf16.h>
#include <math.h>
#include <stdint.h>

#define NUM_HEADS 16
#define DHEAD 64
#define DE 128          // 2*DHEAD per head
#define DMODEL 1024
#define D2 2048
#define BB 4
#define NN 1024
#define MTOT (BB*NN)    // 4096
#define GP 36           // GEMM smem pitch (proven R5 config)
#define WQK 68          // word pitch for bf16x2 Q/K arrays (68 mod 32 = 4 -> bijective)
#define VP  136         // float pitch for raw V tile (136 mod 32 = 8 -> bijective)
#define PP  68          // float pitch for P tiles

// Scratch (device globals; allocation APIs are forbidden)
__device__ float g_Q[(size_t)BB*NUM_HEADS*NN*DE];
__device__ float g_K[(size_t)BB*NUM_HEADS*NN*DE];
__device__ float g_V[(size_t)BB*NUM_HEADS*NN*DE];
__device__ float g_Oc[(size_t)BB*NN*D2];
__device__ float g_lam[NUM_HEADS];

__device__ __forceinline__ uint32_t f2tf(float f) {
    uint32_t u;
    asm("cvt.rna.tf32.f32 %0, %1;" : "=r"(u) : "f"(f));
    return u;
}

__device__ __forceinline__ void mma_tf32(float* d, const uint32_t* a, const uint32_t* b) {
    asm volatile(
        "mma.sync.aligned.m16n8k8.row.col.f32.tf32.tf32.f32 "
        "{%0,%1,%2,%3}, {%4,%5,%6,%7}, {%8,%9}, {%0,%1,%2,%3};"
        : "+f"(d[0]), "+f"(d[1]), "+f"(d[2]), "+f"(d[3])
        : "r"(a[0]), "r"(a[1]), "r"(a[2]), "r"(a[3]), "r"(b[0]), "r"(b[1]));
}

__device__ __forceinline__ void mma_bf16(float* d, const uint32_t* a, const uint32_t* b) {
    asm volatile(
        "mma.sync.aligned.m16n8k16.row.col.f32.bf16.bf16.f32 "
        "{%0,%1,%2,%3}, {%4,%5,%6,%7}, {%8,%9}, {%0,%1,%2,%3};"
        : "+f"(d[0]), "+f"(d[1]), "+f"(d[2]), "+f"(d[3])
        : "r"(a[0]), "r"(a[1]), "r"(a[2]), "r"(a[3]), "r"(b[0]), "r"(b[1]));
}

__device__ __forceinline__ uint32_t bf2u(__nv_bfloat162 v) {
    return *reinterpret_cast<uint32_t*>(&v);
}

// split float4 into bf16 hi pair-words and lo pair-words
__device__ __forceinline__ void split4(float4 v, uint2& h, uint2& l) {
    __nv_bfloat162 H0 = __floats2bfloat162_rn(v.x, v.y);
    __nv_bfloat162 H1 = __floats2bfloat162_rn(v.z, v.w);
    float2 f0 = __bfloat1622float2(H0);
    float2 f1 = __bfloat1622float2(H1);
    __nv_bfloat162 L0 = __floats2bfloat162_rn(v.x - f0.x, v.y - f0.y);
    __nv_bfloat162 L1 = __floats2bfloat162_rn(v.z - f1.x, v.w - f1.y);
    h = make_uint2(bf2u(H0), bf2u(H1));
    l = make_uint2(bf2u(L0), bf2u(L1));
}

// ---------------------------------------------------------------------------
// lambda[h]
// ---------------------------------------------------------------------------
__global__ void lambda_kernel(const float* __restrict__ lq1, const float* __restrict__ lk1,
                              const float* __restrict__ lq2, const float* __restrict__ lk2) {
    int w = threadIdx.x >> 5, lane = threadIdx.x & 31;
    int base = w * 64;
    float s1 = lq1[base+lane]*lk1[base+lane] + lq1[base+32+lane]*lk1[base+32+lane];
    float s2 = lq2[base+lane]*lk2[base+lane] + lq2[base+32+lane]*lk2[base+32+lane];
    #pragma unroll
    for (int off = 16; off; off >>= 1) {
        s1 += __shfl_xor_sync(0xffffffffu, s1, off);
        s2 += __shfl_xor_sync(0xffffffffu, s2, off);
    }
    if (lane == 0) g_lam[w] = expf(s1) - expf(s2) + 0.8f;
}

// ---------------------------------------------------------------------------
// tf32 tensor-core GEMM (R5 proven version, unchanged): C = A @ W^T (NT)
// ---------------------------------------------------------------------------
template<int MODE>
__global__ __launch_bounds__(256, 2) void gemm_tf32(
    const float* __restrict__ A,
    const float* __restrict__ B0, const float* __restrict__ B1, const float* __restrict__ B2,
    float* __restrict__ C0, float* __restrict__ C1, float* __restrict__ C2,
    int K)
{
    __shared__ float As[128][GP];
    __shared__ float Bs[128][GP];

    int t = threadIdx.x;
    int wid = t >> 5, lane = t & 31;
    int row0 = blockIdx.y * 128;

    const float* Bm;
    float* C;
    int col0;
    if (MODE == 1) {
        int which = blockIdx.x >> 4;
        col0 = (blockIdx.x & 15) * 128;
        Bm = (which == 0) ? B0 : ((which == 1) ? B1 : B2);
        C  = (which == 0) ? C0 : ((which == 1) ? C1 : C2);
    } else {
        col0 = blockIdx.x * 128;
        Bm = B0; C = C0;
    }

    int r0 = t >> 3;
    int kq = (t & 7) * 4;
    const float* Ag = A  + (size_t)(row0 + r0) * K + kq;
    const float* Bg = Bm + (size_t)(col0 + r0) * K + kq;

    float4 ar[4], br[4];
    #pragma unroll
    for (int l = 0; l < 4; l++) {
        ar[l] = *(const float4*)(Ag + (size_t)l * 32 * K);
        br[l] = *(const float4*)(Bg + (size_t)l * 32 * K);
    }

    float acc[4][4][4];
    #pragma unroll
    for (int i = 0; i < 4; i++)
        #pragma unroll
        for (int j = 0; j < 4; j++)
            #pragma unroll
            for (int r = 0; r < 4; r++) acc[i][j][r] = 0.f;

    int wm = (wid & 1) * 64;
    int wn = (wid >> 1) * 32;
    int fr = lane >> 2;
    int fc = lane & 3;

    for (int k0 = 0; k0 < K; k0 += 32) {
        #pragma unroll
        for (int l = 0; l < 4; l++) {
            uint4 ua = make_uint4(f2tf(ar[l].x), f2tf(ar[l].y), f2tf(ar[l].z), f2tf(ar[l].w));
            *(uint4*)&As[r0 + l*32][kq] = ua;
            uint4 ub = make_uint4(f2tf(br[l].x), f2tf(br[l].y), f2tf(br[l].z), f2tf(br[l].w));
            *(uint4*)&Bs[r0 + l*32][kq] = ub;
        }
        __syncthreads();

        if (k0 + 32 < K) {
            #pragma unroll
            for (int l = 0; l < 4; l++) {
                ar[l] = *(const float4*)(Ag + (size_t)l * 32 * K + k0 + 32);
                br[l] = *(const float4*)(Bg + (size_t)l * 32 * K + k0 + 32);
            }
        }

        #pragma unroll
        for (int kc = 0; kc < 32; kc += 8) {
            uint32_t af[4][4], bf[4][2];
            #pragma unroll
            for (int i = 0; i < 4; i++) {
                af[i][0] = __float_as_uint(As[wm + i*16 +     fr][kc +     fc]);
                af[i][1] = __float_as_uint(As[wm + i*16 + 8 + fr][kc +     fc]);
                af[i][2] = __float_as_uint(As[wm + i*16 +     fr][kc + 4 + fc]);
                af[i][3] = __float_as_uint(As[wm + i*16 + 8 + fr][kc + 4 + fc]);
            }
            #pragma unroll
            for (int j = 0; j < 4; j++) {
                bf[j][0] = __float_as_uint(Bs[wn + j*8 + fr][kc +     fc]);
                bf[j][1] = __float_as_uint(Bs[wn + j*8 + fr][kc + 4 + fc]);
            }
            #pragma unroll
            for (int i = 0; i < 4; i++)
                #pragma unroll
                for (int j = 0; j < 4; j++)
                    mma_tf32(acc[i][j], af[i], bf[j]);
        }
        __syncthreads();
    }

    #pragma unroll
    for (int i = 0; i < 4; i++) {
        int rr = row0 + wm + i*16 + fr;
        #pragma unroll
        for (int j = 0; j < 4; j++) {
            int cc = col0 + wn + j*8 + fc*2;
            float2 v0 = make_float2(acc[i][j][0], acc[i][j][1]);
            float2 v1 = make_float2(acc[i][j][2], acc[i][j][3]);
            if (MODE == 0) {
                *(float2*)(C + (size_t)rr * DMODEL + cc) = v0;
                *(float2*)(C + (size_t)(rr + 8) * DMODEL + cc) = v1;
            } else {
                int h = cc >> 7, e = cc & 127;
                int bb = rr >> 10, n = rr & 1023;
                *(float2*)(C + (((size_t)(bb*NUM_HEADS + h) * NN + n) * DE + e)) = v0;
                int rr2 = rr + 8;
                bb = rr2 >> 10; n = rr2 & 1023;
                *(float2*)(C + (((size_t)(bb*NUM_HEADS + h) * NN + n) * DE + e)) = v1;
            }
        }
    }
}

// ---------------------------------------------------------------------------
// Dual-stream flash attention, occupancy-2 version:
//  - logits: bf16 hi/lo 3-product mma.m16n8k16 (fp32-grade accuracy)
//  - V overlays the K smem buffer; loaded via cp.async AFTER logits, latency
//    hidden under softmax; converted to tf32 (RNA) at PV fragment load
//  - PV: tf32 mma (P written tf32 as before)
//  - deferred softmax denominator; LPT causal remap
// smem = 106496 B -> 2 blocks/SM. Grid: (N/64, B*H). 256 threads = 8 warps.
// ---------------------------------------------------------------------------
__global__ __launch_bounds__(256, 2) void attn_kernel(const float* __restrict__ rms_scale) {
    extern __shared__ float sm[];
    // word (uint32) views for bf16x2 arrays
    uint32_t* Qh = (uint32_t*)sm;              // 64 x WQK words
    uint32_t* Ql = Qh + 64*WQK;                // 64 x WQK
    uint32_t* Kh = Ql + 64*WQK;                // 64 x WQK  (union with V)
    uint32_t* Kl = Kh + 64*WQK;                // 64 x WQK
    float*    Vs = (float*)Kh;                 // 64 x VP raw fp32 (overlays Kh+Kl)
    float*    P1 = (float*)(Kl + 64*WQK);      // 64 x PP tf32
    float*    P2 = P1 + 64*PP;
    float*   bm1 = P2 + 64*PP;                 // [2][64] row-max exchange
    float*   bm2 = bm1 + 128;
    float*   bs1 = bm2 + 128;                  // [2][64] final l exchange
    float*   bs2 = bs1 + 128;

    int t  = threadIdx.x;
    int bh = blockIdx.y;
    int h  = bh & (NUM_HEADS - 1);
    int b  = bh >> 4;
    int qi = gridDim.x - 1 - blockIdx.x;   // LPT: long tiles first
    int qb = qi * 64;
    const float* Qp = g_Q + (size_t)bh * NN * DE;
    const float* Kp = g_K + (size_t)bh * NN * DE;
    const float* Vp = g_V + (size_t)bh * NN * DE;

    int lane = t & 31, wid = t >> 5;
    int gid = lane >> 2, tig = lane & 3;
    int rt = (wid >> 1) * 16;
    int half = wid & 1;
    int ch = half * 32;     // score col-half
    int nh = half * 64;     // PV col-half
    int rA = rt + gid, rB = rt + gid + 8;

    uint32_t vsm0 = (uint32_t)__cvta_generic_to_shared(Vs);

    // load Q tile (64x128), split into bf16 hi/lo words
    #pragma unroll
    for (int l = 0; l < 8; l++) {
        int c = t + l*256;
        int r = c >> 5, dq = (c & 31) * 4;
        float4 q = *(const float4*)(Qp + (size_t)(qb + r)*DE + dq);
        uint2 hw, lw;
        split4(q, hw, lw);
        int wi = r*WQK + (dq >> 1);
        *(uint2*)&Qh[wi] = hw;
        *(uint2*)&Ql[wi] = lw;
    }

    float m1a = -1e30f, m1b = -1e30f, m2a = -1e30f, m2b = -1e30f;
    float l1a = 0.f, l1b = 0.f, l2a = 0.f, l2b = 0.f;   // per-thread partials
    float o1[8][4], o2[8][4];
    #pragma unroll
    for (int f = 0; f < 8; f++)
        #pragma unroll
        for (int r = 0; r < 4; r++) { o1[f][r] = 0.f; o2[f][r] = 0.f; }

    float lam = g_lam[h];

    int nkb = qi + 1;   // causal: key blocks 0..qi
    for (int jb = 0; jb < nkb; jb++) {
        int kb = jb * 64;

        // ---- stage K (bf16 hi/lo split) into the K/V union buffer ----
        #pragma unroll
        for (int l = 0; l < 8; l++) {
            int c = t + l*256;
            int r = c >> 5, dq = (c & 31) * 4;
            float4 kq = *(const float4*)(Kp + (size_t)(kb + r)*DE + dq);
            uint2 hw, lw;
            split4(kq, hw, lw);
            int wi = r*WQK + (dq >> 1);
            *(uint2*)&Kh[wi] = hw;
            *(uint2*)&Kl[wi] = lw;
        }
        __syncthreads();   // (1) K staged (prev PV finished at loop-end sync)

        // ---- logits: 3-product bf16 mma ----
        float s1[4][4], s2[4][4];
        #pragma unroll
        for (int i = 0; i < 4; i++)
            #pragma unroll
            for (int j = 0; j < 4; j++) { s1[i][j] = 0.f; s2[i][j] = 0.f; }

        #pragma unroll
        for (int kcw = 0; kcw < 4; kcw++) {   // 16-k chunks over dhead=64
            int wb1 = kcw * 8;                // word base, stream 1 (k 0..63)
            int wb2 = 32 + kcw * 8;           // word base, stream 2 (k 64..127)
            uint32_t ah[4], al[4];
            // stream 1
            ah[0] = Qh[rA*WQK + wb1 + tig];     ah[1] = Qh[rB*WQK + wb1 + tig];
            ah[2] = Qh[rA*WQK + wb1 + 4 + tig]; ah[3] = Qh[rB*WQK + wb1 + 4 + tig];
            al[0] = Ql[rA*WQK + wb1 + tig];     al[1] = Ql[rB*WQK + wb1 + tig];
            al[2] = Ql[rA*WQK + wb1 + 4 + tig]; al[3] = Ql[rB*WQK + wb1 + 4 + tig];
            #pragma unroll
            for (int nt = 0; nt < 4; nt++) {
                int n0 = ch + nt*8 + gid;
                uint32_t bhf[2], blf[2];
                bhf[0] = Kh[n0*WQK + wb1 + tig];
                bhf[1] = Kh[n0*WQK + wb1 + 4 + tig];
                blf[0] = Kl[n0*WQK + wb1 + tig];
                blf[1] = Kl[n0*WQK + wb1 + 4 + tig];
                mma_bf16(s1[nt], ah, bhf);
                mma_bf16(s1[nt], al, bhf);
                mma_bf16(s1[nt], ah, blf);
            }
            // stream 2
            ah[0] = Qh[rA*WQK + wb2 + tig];     ah[1] = Qh[rB*WQK + wb2 + tig];
            ah[2] = Qh[rA*WQK + wb2 + 4 + tig]; ah[3] = Qh[rB*WQK + wb2 + 4 + tig];
            al[0] = Ql[rA*WQK + wb2 + tig];     al[1] = Ql[rB*WQK + wb2 + tig];
            al[2] = Ql[rA*WQK + wb2 + 4 + tig]; al[3] = Ql[rB*WQK + wb2 + 4 + tig];
            #pragma unroll
            for (int nt = 0; nt < 4; nt++) {
                int n0 = ch + nt*8 + gid;
                uint32_t bhf[2], blf[2];
                bhf[0] = Kh[n0*WQK + wb2 + tig];
                bhf[1] = Kh[n0*WQK + wb2 + 4 + tig];
                blf[0] = Kl[n0*WQK + wb2 + tig];
                blf[1] = Kl[n0*WQK + wb2 + 4 + tig];
                mma_bf16(s2[nt], ah, bhf);
                mma_bf16(s2[nt], al, bhf);
                mma_bf16(s2[nt], ah, blf);
            }
        }

        // ---- scale (+ diagonal mask) ----
        bool last = (jb == nkb - 1);
        #pragma unroll
        for (int nt = 0; nt < 4; nt++)
            #pragma unroll
            for (int c = 0; c < 4; c++) {
                float v1 = s1[nt][c] * 0.125f;
                float v2 = s2[nt][c] * 0.125f;
                if (last) {
                    int col = ch + nt*8 + 2*tig + (c & 1);
                    int row = rt + gid + ((c & 2) ? 8 : 0);
                    if (col > row) { v1 = -1e30f; v2 = -1e30f; }
                }
                s1[nt][c] = v1; s2[nt][c] = v2;
            }

        // ---- row max (own 32 cols -> cross-half exchange) ----
        float mt1a = -1e30f, mt1b = -1e30f, mt2a = -1e30f, mt2b = -1e30f;
        #pragma unroll
        for (int nt = 0; nt < 4; nt++) {
            mt1a = fmaxf(mt1a, fmaxf(s1[nt][0], s1[nt][1]));
            mt1b = fmaxf(mt1b, fmaxf(s1[nt][2], s1[nt][3]));
            mt2a = fmaxf(mt2a, fmaxf(s2[nt][0], s2[nt][1]));
            mt2b = fmaxf(mt2b, fmaxf(s2[nt][2], s2[nt][3]));
        }
        #pragma unroll
        for (int off = 1; off <= 2; off <<= 1) {
            mt1a = fmaxf(mt1a, __shfl_xor_sync(0xffffffffu, mt1a, off));
            mt1b = fmaxf(mt1b, __shfl_xor_sync(0xffffffffu, mt1b, off));
            mt2a = fmaxf(mt2a, __shfl_xor_sync(0xffffffffu, mt2a, off));
            mt2b = fmaxf(mt2b, __shfl_xor_sync(0xffffffffu, mt2b, off));
        }
        if (tig == 0) {
            bm1[half*64 + rA] = mt1a; bm1[half*64 + rB] = mt1b;
            bm2[half*64 + rA] = mt2a; bm2[half*64 + rB] = mt2b;
        }
        __syncthreads();   // (A) logits reads of K done block-wide; maxes visible

        // ---- issue V cp.async into the K/V union buffer (overlaps softmax) ----
        #pragma unroll
        for (int l = 0; l < 8; l++) {
            int c = t + l*256;
            int r = c >> 5, dq = (c & 31) * 4;
            uint32_t dst = vsm0 + (uint32_t)((r*VP + dq) * 4);
            const float* src = Vp + (size_t)(kb + r)*DE + dq;
            asm volatile("cp.async.cg.shared.global [%0], [%1], 16;" :: "r"(dst), "l"(src));
        }
        asm volatile("cp.async.commit_group;" ::: "memory");

        // ---- softmax: M, c, exp, write tf32 P, deferred l ----
        float M1a = fmaxf(m1a, fmaxf(bm1[rA], bm1[64 + rA]));
        float M1b = fmaxf(m1b, fmaxf(bm1[rB], bm1[64 + rB]));
        float M2a = fmaxf(m2a, fmaxf(bm2[rA], bm2[64 + rA]));
        float M2b = fmaxf(m2b, fmaxf(bm2[rB], bm2[64 + rB]));
        float c1a = __expf(m1a - M1a), c1b = __expf(m1b - M1b);
        float c2a = __expf(m2a - M2a), c2b = __expf(m2b - M2b);
        m1a = M1a; m1b = M1b; m2a = M2a; m2b = M2b;

        float ps1a = 0.f, ps1b = 0.f, ps2a = 0.f, ps2b = 0.f;
        #pragma unroll
        for (int nt = 0; nt < 4; nt++) {
            int colb = ch + nt*8 + 2*tig;
            float p0 = __uint_as_float(f2tf(__expf(s1[nt][0] - M1a)));
            float p1 = __uint_as_float(f2tf(__expf(s1[nt][1] - M1a)));
            float p2 = __uint_as_float(f2tf(__expf(s1[nt][2] - M1b)));
            float p3 = __uint_as_float(f2tf(__expf(s1[nt][3] - M1b)));
            ps1a += p0 + p1; ps1b += p2 + p3;
            *(float2*)&P1[rA*PP + colb] = make_float2(p0, p1);
            *(float2*)&P1[rB*PP + colb] = make_float2(p2, p3);
            float q0 = __uint_as_float(f2tf(__expf(s2[nt][0] - M2a)));
            float q1 = __uint_as_float(f2tf(__expf(s2[nt][1] - M2a)));
            float q2 = __uint_as_float(f2tf(__expf(s2[nt][2] - M2b)));
            float q3 = __uint_as_float(f2tf(__expf(s2[nt][3] - M2b)));
            ps2a += q0 + q1; ps2b += q2 + q3;
            *(float2*)&P2[rA*PP + colb] = make_float2(q0, q1);
            *(float2*)&P2[rB*PP + colb] = make_float2(q2, q3);
        }
        l1a = l1a*c1a + ps1a;
        l1b = l1b*c1b + ps1b;
        l2a = l2a*c2a + ps2a;
        l2b = l2b*c2b + ps2b;

        asm volatile("cp.async.wait_group 0;" ::: "memory");
        __syncthreads();   // (B) P visible block-wide; V arrived in all lanes

        // ---- P @ V on tensor cores (V converted tf32 at load) ----
        #pragma unroll
        for (int f = 0; f < 8; f++) {
            o1[f][0] *= c1a; o1[f][1] *= c1a; o1[f][2] *= c1b; o1[f][3] *= c1b;
            o2[f][0] *= c2a; o2[f][1] *= c2a; o2[f][2] *= c2b; o2[f][3] *= c2b;
        }
        #pragma unroll
        for (int kc = 0; kc < 64; kc += 8) {
            uint32_t a1f[4], a2f[4];
            a1f[0] = __float_as_uint(P1[rA*PP + kc + tig]);
            a1f[1] = __float_as_uint(P1[rB*PP + kc + tig]);
            a1f[2] = __float_as_uint(P1[rA*PP + kc + tig + 4]);
            a1f[3] = __float_as_uint(P1[rB*PP + kc + tig + 4]);
            a2f[0] = __float_as_uint(P2[rA*PP + kc + tig]);
            a2f[1] = __float_as_uint(P2[rB*PP + kc + tig]);
            a2f[2] = __float_as_uint(P2[rA*PP + kc + tig + 4]);
            a2f[3] = __float_as_uint(P2[rB*PP + kc + tig + 4]);
            #pragma unroll
            for (int f = 0; f < 8; f++) {
                uint32_t bf[2];
                bf[0] = f2tf(Vs[(kc + tig    )*VP + nh + f*8 + gid]);
                bf[1] = f2tf(Vs[(kc + tig + 4)*VP + nh + f*8 + gid]);
                mma_tf32(o1[f], a1f, bf);
                mma_tf32(o2[f], a2f, bf);
            }
        }
        __syncthreads();   // (C) PV reads of V done before next K staging
    }

    // ---- finalize: reduce l, combine, RMS-norm, write Oc ----
    #pragma unroll
    for (int off = 1; off <= 2; off <<= 1) {
        l1a += __shfl_xor_sync(0xffffffffu, l1a, off);
        l1b += __shfl_xor_sync(0xffffffffu, l1b, off);
        l2a += __shfl_xor_sync(0xffffffffu, l2a, off);
        l2b += __shfl_xor_sync(0xffffffffu, l2b, off);
    }
    if (tig == 0) {
        bs1[half*64 + rA] = l1a; bs1[half*64 + rB] = l1b;
        bs2[half*64 + rA] = l2a; bs2[half*64 + rB] = l2b;
    }
    __syncthreads();
    float il1a = 1.0f / (bs1[rA] + bs1[64 + rA]);
    float il1b = 1.0f / (bs1[rB] + bs1[64 + rB]);
    float il2a = 1.0f / (bs2[rA] + bs2[64 + rA]);
    float il2b = 1.0f / (bs2[rB] + bs2[64 + rB]);

    float ssA = 0.f, ssB = 0.f;
    #pragma unroll
    for (int f = 0; f < 8; f++) {
        o1[f][0] = o1[f][0]*il1a - lam*o2[f][0]*il2a;
        o1[f][1] = o1[f][1]*il1a - lam*o2[f][1]*il2a;
        o1[f][2] = o1[f][2]*il1b - lam*o2[f][2]*il2b;
        o1[f][3] = o1[f][3]*il1b - lam*o2[f][3]*il2b;
        ssA += o1[f][0]*o1[f][0] + o1[f][1]*o1[f][1];
        ssB += o1[f][2]*o1[f][2] + o1[f][3]*o1[f][3];
    }
    ssA += __shfl_xor_sync(0xffffffffu, ssA, 1);
    ssA += __shfl_xor_sync(0xffffffffu, ssA, 2);
    ssB += __shfl_xor_sync(0xffffffffu, ssB, 1);
    ssB += __shfl_xor_sync(0xffffffffu, ssB, 2);

    if (tig == 0) {
        float* dst = half ? bm2 : bm1;
        dst[rA] = ssA;
        dst[rB] = ssB;
    }
    __syncthreads();
    float totA = bm1[rA] + bm2[rA];
    float totB = bm1[rB] + bm2[rB];
    float scA = rsqrtf(totA * (1.0f/128.0f) + 1e-5f) * 0.2f;
    float scB = rsqrtf(totB * (1.0f/128.0f) + 1e-5f) * 0.2f;

    size_t obaseA = ((size_t)b * NN + qb + rA) * D2 + h * DE;
    size_t obaseB = ((size_t)b * NN + qb + rB) * D2 + h * DE;
    #pragma unroll
    for (int f = 0; f < 8; f++) {
        int col = nh + f*8 + 2*tig;
        float2 rs = *(const float2*)(rms_scale + col);
        *(float2*)(g_Oc + obaseA + col) = make_float2(o1[f][0]*scA*rs.x, o1[f][1]*scA*rs.y);
        *(float2*)(g_Oc + obaseB + col) = make_float2(o1[f][2]*scB*rs.x, o1[f][3]*scB*rs.y);
    }
}

// ---------------------------------------------------------------------------
// Host launcher
// ---------------------------------------------------------------------------
// smem floats: Qh/Ql words 2*4352 + K/V union 8704 + P 2*4352 + exch 512 = 26624
#define ATTN_SMEM (26624 * 4)   // 106496 bytes -> 2 blocks/SM

extern "C" void kernel_launch(void* const* d_in, const int* in_sizes, int n_in,
                              void* d_out, int out_size) {
    const float* X   = (const float*)d_in[0];
    const float* Wq  = (const float*)d_in[1];
    const float* Wk  = (const float*)d_in[2];
    const float* Wv  = (const float*)d_in[3];
    const float* Wo  = (const float*)d_in[4];
    const float* lq1 = (const float*)d_in[5];
    const float* lk1 = (const float*)d_in[6];
    const float* lq2 = (const float*)d_in[7];
    const float* lk2 = (const float*)d_in[8];
    const float* rms = (const float*)d_in[9];

    float *pQ, *pK, *pV, *pOc;
    cudaGetSymbolAddress((void**)&pQ,  g_Q);
    cudaGetSymbolAddress((void**)&pK,  g_K);
    cudaGetSymbolAddress((void**)&pV,  g_V);
    cudaGetSymbolAddress((void**)&pOc, g_Oc);

    lambda_kernel<<<1, 512>>>(lq1, lk1, lq2, lk2);

    dim3 gqkv(48, MTOT/128);
    gemm_tf32<1><<<gqkv, 256>>>(X, Wq, Wk, Wv, pQ, pK, pV, DMODEL);

    cudaFuncSetAttribute(attn_kernel, cudaFuncAttributeMaxDynamicSharedMemorySize, ATTN_SMEM);
    attn_kernel<<<dim3(NN/64, BB*NUM_HEADS), 256, ATTN_SMEM>>>(rms);

    dim3 gout(DMODEL/128, MTOT/128);
    gemm_tf32<0><<<gout, 256>>>(pOc, Wo, nullptr, nullptr, (float*)d_out, nullptr, nullptr, D2);
}